// round 4
// baseline (speedup 1.0000x reference)
#include <cuda_runtime.h>

#define BATCH  32768
#define NPG    54
#define EPG    144
#define GLOB   10
#define CONCAT 226
#define CPAD   228   // padded row stride (16B multiple) for g_concat
#define EDGES_TOTAL (BATCH*EPG)
#define TB     64    // rows per CTA in out-MLP GEMM

// Scratch for the [B, 228] padded concat activations (device global).
static __device__ __align__(16) float g_concat[(size_t)BATCH * CPAD];

// ---------------------------------------------------------------------------
// Kernel A: per-graph fused GraphConv1 -> relu -> GraphConv2 -> relu,
// plus global-feature MLP; writes concat([embeds(216), g(10)]) row.
// One CTA per graph, 128 threads.
// ---------------------------------------------------------------------------
__global__ __launch_bounds__(128) void conv_kernel(
    const float* __restrict__ x,      const int*   __restrict__ eidx,
    const float* __restrict__ eattr,  const float* __restrict__ gfeat,
    const float* __restrict__ W_rel1, const float* __restrict__ b1,
    const float* __restrict__ W_root1,
    const float* __restrict__ W_rel2, const float* __restrict__ b2,
    const float* __restrict__ W_root2,
    const float* __restrict__ Wg1, const float* __restrict__ bg1,
    const float* __restrict__ Wg2, const float* __restrict__ bg2,
    const float* __restrict__ Wg3, const float* __restrict__ bg3)
{
    __shared__ __align__(16) float xs[NPG * 8];
    __shared__ float agg[NPG * 8];
    __shared__ float h1s[NPG * 16];
    __shared__ float agg2[NPG * 16];
    __shared__ __align__(16) float h2s[NPG * 4];
    __shared__ float gins[GLOB], g1s[8], g2s[8], gsm[GLOB];
    __shared__ int   es[EPG], ed[EPG];
    __shared__ float ew[EPG];
    __shared__ float wsm[654];

    const int g    = blockIdx.x;
    const int t    = threadIdx.x;
    const int base = g * NPG;

    // ---- stage inputs (x rows: g*432 floats = g*1728 bytes, 16B aligned) ----
    {
        const float4* xg4 = (const float4*)(x + (size_t)base * 8);
        float4*       xs4 = (float4*)xs;
        for (int i = t; i < NPG * 2; i += 128) xs4[i] = xg4[i];
    }
    for (int i = t; i < NPG * 8; i += 128) agg[i] = 0.f;
    for (int i = t; i < NPG * 16; i += 128) agg2[i] = 0.f;

    const int*   sp = eidx + (size_t)g * EPG;
    const int*   dp = eidx + (size_t)EDGES_TOTAL + (size_t)g * EPG;
    const float* ap = eattr + (size_t)g * EPG;
    for (int e = t; e < EPG; e += 128) {
        es[e] = sp[e] - base;
        ed[e] = dp[e] - base;
        ew[e] = ap[e];
    }
    if (t < GLOB) gins[t] = gfeat[g * GLOB + t];

    // ---- stage weights into smem ----
    {
        const float* ptrs[12] = {W_rel1, b1, W_root1, W_rel2, b2, W_root2,
                                 Wg1, bg1, Wg2, bg2, Wg3, bg3};
        const int szs[12] = {128, 16, 128, 64, 4, 64, 80, 8, 64, 8, 80, 10};
        const int ofs[12] = {0, 128, 144, 272, 336, 340, 404, 484, 492, 556, 564, 644};
        for (int a = 0; a < 12; a++)
            for (int i = t; i < szs[a]; i += 128) wsm[ofs[a] + i] = ptrs[a][i];
    }
    __syncthreads();

    // ---- conv1 edge aggregation: agg[dst] += w * x[src] ----
    for (int i = t; i < EPG * 8; i += 128) {
        int e = i >> 3, f = i & 7;
        atomicAdd(&agg[ed[e] * 8 + f], ew[e] * xs[es[e] * 8 + f]);
    }
    __syncthreads();

    // ---- h1 = relu(agg @ W_rel1 + b1 + x @ W_root1) : [54,16] ----
    for (int i = t; i < NPG * 16; i += 128) {
        int v = i >> 4, o = i & 15;
        float a = wsm[128 + o];
        #pragma unroll
        for (int c = 0; c < 8; c++)
            a += agg[v * 8 + c] * wsm[c * 16 + o] + xs[v * 8 + c] * wsm[144 + c * 16 + o];
        h1s[i] = fmaxf(a, 0.f);
    }
    __syncthreads();

    // ---- conv2 edge aggregation: agg2[dst] += w * h1[src] ----
    for (int i = t; i < EPG * 16; i += 128) {
        int e = i >> 4, f = i & 15;
        atomicAdd(&agg2[ed[e] * 16 + f], ew[e] * h1s[es[e] * 16 + f]);
    }
    __syncthreads();

    // ---- h2 = relu(agg2 @ W_rel2 + b2 + h1 @ W_root2) : [54,4] ----
    for (int i = t; i < NPG * 4; i += 128) {
        int v = i >> 2, o = i & 3;
        float a = wsm[336 + o];
        #pragma unroll
        for (int c = 0; c < 16; c++)
            a += agg2[v * 16 + c] * wsm[272 + c * 4 + o] + h1s[v * 16 + c] * wsm[340 + c * 4 + o];
        h2s[i] = fmaxf(a, 0.f);
    }
    // ---- global MLP layer 1 (overlapped with h2) ----
    if (t < 8) {
        float a = wsm[484 + t];
        #pragma unroll
        for (int i = 0; i < GLOB; i++) a += gins[i] * wsm[404 + i * 8 + t];
        g1s[t] = fmaxf(a, 0.f);
    }
    __syncthreads();
    if (t < 8) {
        float a = wsm[556 + t];
        #pragma unroll
        for (int i = 0; i < 8; i++) a += g1s[i] * wsm[492 + i * 8 + t];
        g2s[t] = fmaxf(a, 0.f);
    }
    __syncthreads();
    if (t < GLOB) {
        float a = wsm[644 + t];
        #pragma unroll
        for (int i = 0; i < 8; i++) a += g2s[i] * wsm[564 + i * 10 + t];  // Wg3 is (8,10): stride 10
        gsm[t] = fmaxf(a, 0.f);
    }
    __syncthreads();

    // ---- write concat row: padded stride 228 -> row base g*912B, 16B aligned ----
    float* op = g_concat + (size_t)g * CPAD;
    {
        const float4* s4 = (const float4*)h2s;
        float4*       o4 = (float4*)op;
        for (int i = t; i < NPG; i += 128)   // 54 float4 = 216 floats
            o4[i] = s4[i];
    }
    if (t < GLOB + 2) {                      // 10 globals + 2 pad zeros
        op[NPG * 4 + t] = (t < GLOB) ? gsm[t] : 0.f;
    }
}

// ---------------------------------------------------------------------------
// Kernel B: out = sigmoid(relu(concat @ Wo1 + bo1) @ Wo2 + bo2)
// Tiled fp32 GEMM: full Wo1 (226x128) in smem + 64 input rows (stride 228).
// 256 threads: warp w owns rows w*8..w*8+7, lane owns 4 columns.
// ---------------------------------------------------------------------------
__global__ __launch_bounds__(256) void mlp_kernel(
    const float* __restrict__ Wo1, const float* __restrict__ bo1,
    const float* __restrict__ Wo2, const float* __restrict__ bo2,
    float* __restrict__ out)
{
    extern __shared__ float sm[];
    float* ws  = sm;                 // [226*128]
    float* ins = sm + CONCAT * 128;  // [64*228]

    const int t  = threadIdx.x;
    const int g0 = blockIdx.x * TB;

    // stage Wo1 (226*128 floats = 28928, /4 = 7232 float4) and 64 padded rows
    // (64*228 = 14592 floats = 3648 float4; block base g0*228*4 B, 16B mult.)
    {
        const float4* wsrc = (const float4*)Wo1;
        float4*       wdst = (float4*)ws;
        for (int i = t; i < CONCAT * 128 / 4; i += 256) wdst[i] = wsrc[i];
        const float4* csrc = (const float4*)(g_concat + (size_t)g0 * CPAD);
        float4*       cdst = (float4*)ins;
        for (int i = t; i < TB * CPAD / 4; i += 256) cdst[i] = csrc[i];
    }
    __syncthreads();

    const int lane = t & 31;
    const int j0   = lane * 4;         // 4 output columns
    const int r0   = (t >> 5) * 8;     // 8 rows per warp

    float acc[8][4];
    #pragma unroll
    for (int r = 0; r < 8; r++)
        #pragma unroll
        for (int c = 0; c < 4; c++) acc[r][c] = 0.f;

    #pragma unroll 2
    for (int k = 0; k < CONCAT; k++) {
        float4 w = *(const float4*)&ws[k * 128 + j0];
        #pragma unroll
        for (int r = 0; r < 8; r++) {
            float v = ins[(r0 + r) * CPAD + k];
            acc[r][0] += v * w.x;
            acc[r][1] += v * w.y;
            acc[r][2] += v * w.z;
            acc[r][3] += v * w.w;
        }
    }

    const float4 bv  = *(const float4*)&bo1[j0];
    const float4 wv  = *(const float4*)&Wo2[j0];
    const float bo2s = bo2[0];

    #pragma unroll
    for (int r = 0; r < 8; r++) {
        float p = fmaxf(acc[r][0] + bv.x, 0.f) * wv.x
                + fmaxf(acc[r][1] + bv.y, 0.f) * wv.y
                + fmaxf(acc[r][2] + bv.z, 0.f) * wv.z
                + fmaxf(acc[r][3] + bv.w, 0.f) * wv.w;
        #pragma unroll
        for (int off = 16; off; off >>= 1)
            p += __shfl_down_sync(0xffffffffu, p, off);
        if (lane == 0)
            out[g0 + r0 + r] = 1.f / (1.f + expf(-(p + bo2s)));
    }
}

// ---------------------------------------------------------------------------
extern "C" void kernel_launch(void* const* d_in, const int* in_sizes, int n_in,
                              void* d_out, int out_size)
{
    const float* x       = (const float*)d_in[0];
    const int*   eidx    = (const int*)  d_in[1];
    const float* eattr   = (const float*)d_in[2];
    const float* gfeat   = (const float*)d_in[3];
    const float* W_rel1  = (const float*)d_in[4];
    const float* b1      = (const float*)d_in[5];
    const float* W_root1 = (const float*)d_in[6];
    const float* W_rel2  = (const float*)d_in[7];
    const float* b2      = (const float*)d_in[8];
    const float* W_root2 = (const float*)d_in[9];
    const float* Wg1     = (const float*)d_in[10];
    const float* bg1     = (const float*)d_in[11];
    const float* Wg2     = (const float*)d_in[12];
    const float* bg2     = (const float*)d_in[13];
    const float* Wg3     = (const float*)d_in[14];
    const float* bg3     = (const float*)d_in[15];
    const float* Wo1     = (const float*)d_in[16];
    const float* bo1     = (const float*)d_in[17];
    const float* Wo2     = (const float*)d_in[18];
    const float* bo2     = (const float*)d_in[19];
    // d_in[20] = isTrain (eval mode: dropout is identity)

    conv_kernel<<<BATCH, 128>>>(x, eidx, eattr, gfeat,
                                W_rel1, b1, W_root1, W_rel2, b2, W_root2,
                                Wg1, bg1, Wg2, bg2, Wg3, bg3);

    const int smem_bytes = (CONCAT * 128 + TB * CPAD) * (int)sizeof(float);
    cudaFuncSetAttribute(mlp_kernel, cudaFuncAttributeMaxDynamicSharedMemorySize,
                         smem_bytes);
    mlp_kernel<<<BATCH / TB, 256, smem_bytes>>>(Wo1, bo1, Wo2, bo2,
                                                (float*)d_out);
}

// round 5
// speedup vs baseline: 1.1881x; 1.1881x over previous
#include <cuda_runtime.h>

#define BATCH  32768
#define NPG    54
#define EPG    144
#define GLOB   10
#define CONCAT 226
#define CPAD   228   // padded row stride (16B multiple) for g_concat
#define EDGES_TOTAL (BATCH*EPG)
#define TB     64    // rows per CTA in out-MLP GEMM
#define GPC    32    // graphs per conv CTA (32768 = 1024 * 32)

// Scratch for the [B, 228] padded concat activations (device global).
static __device__ __align__(16) float g_concat[(size_t)BATCH * CPAD];

// ---------------- packed f32x2 helpers (sm_103a) ----------------
__device__ __forceinline__ unsigned long long pk(float lo, float hi) {
    unsigned long long r;
    asm("mov.b64 %0, {%1,%2};" : "=l"(r) : "f"(lo), "f"(hi));
    return r;
}
__device__ __forceinline__ unsigned long long f2fma(unsigned long long a,
                                                    unsigned long long b,
                                                    unsigned long long c) {
    unsigned long long d;
    asm("fma.rn.f32x2 %0, %1, %2, %3;" : "=l"(d) : "l"(a), "l"(b), "l"(c));
    return d;
}
__device__ __forceinline__ void upk(unsigned long long v, float& lo, float& hi) {
    asm("mov.b64 {%0,%1}, %2;" : "=f"(lo), "=f"(hi) : "l"(v));
}

// ---------------- cp.async helpers ----------------
__device__ __forceinline__ void cpa16(void* s, const void* g) {
    unsigned ss = (unsigned)__cvta_generic_to_shared(s);
    asm volatile("cp.async.ca.shared.global [%0], [%1], 16;\n" :: "r"(ss), "l"(g));
}
__device__ __forceinline__ void cpa4(void* s, const void* g) {
    unsigned ss = (unsigned)__cvta_generic_to_shared(s);
    asm volatile("cp.async.ca.shared.global [%0], [%1], 4;\n" :: "r"(ss), "l"(g));
}
#define CP_COMMIT() asm volatile("cp.async.commit_group;\n" ::: "memory")
#define CP_WAIT0()  asm volatile("cp.async.wait_group 0;\n" ::: "memory")

// ---------------------------------------------------------------------------
// Kernel G: global-feature MLP (10 -> 8 -> 8 -> 10), one thread per graph.
// Writes g_concat[g*CPAD + 216 .. 227] (incl. 2 zero pads).
// ---------------------------------------------------------------------------
__global__ __launch_bounds__(256) void glob_kernel(
    const float* __restrict__ gfeat,
    const float* __restrict__ Wg1, const float* __restrict__ bg1,
    const float* __restrict__ Wg2, const float* __restrict__ bg2,
    const float* __restrict__ Wg3, const float* __restrict__ bg3)
{
    __shared__ float ws[250];
    const int t = threadIdx.x;
    // stage: Wg1 80 @0, bg1 8 @80, Wg2 64 @88, bg2 8 @152, Wg3 80 @160, bg3 10 @240
    if (t < 80)  ws[t]        = Wg1[t];
    if (t < 8)   ws[80 + t]   = bg1[t];
    if (t < 64)  ws[88 + t]   = Wg2[t];
    if (t < 8)   ws[152 + t]  = bg2[t];
    if (t < 80)  ws[160 + t]  = Wg3[t];
    if (t < 10)  ws[240 + t]  = bg3[t];
    __syncthreads();

    const int g = blockIdx.x * 256 + t;
    float gi[GLOB];
    #pragma unroll
    for (int i = 0; i < GLOB; i++) gi[i] = gfeat[g * GLOB + i];

    float a1[8];
    #pragma unroll
    for (int o = 0; o < 8; o++) {
        float a = ws[80 + o];
        #pragma unroll
        for (int i = 0; i < GLOB; i++) a += gi[i] * ws[i * 8 + o];
        a1[o] = fmaxf(a, 0.f);
    }
    float a2[8];
    #pragma unroll
    for (int o = 0; o < 8; o++) {
        float a = ws[152 + o];
        #pragma unroll
        for (int i = 0; i < 8; i++) a += a1[i] * ws[88 + i * 8 + o];
        a2[o] = fmaxf(a, 0.f);
    }
    float* op = g_concat + (size_t)g * CPAD + NPG * 4;
    #pragma unroll
    for (int o = 0; o < GLOB; o++) {
        float a = ws[240 + o];
        #pragma unroll
        for (int i = 0; i < 8; i++) a += a2[i] * ws[160 + i * 10 + o];
        op[o] = fmaxf(a, 0.f);
    }
    op[10] = 0.f; op[11] = 0.f;   // pads
}

// ---------------------------------------------------------------------------
// Kernel A: persistent per-graph fused GraphConv1 -> relu -> GraphConv2 -> relu.
// 1024 CTAs x 128 threads, GPC graphs each, cp.async double-buffered inputs.
// Conv2 uses linearity: aggregate p = h1 @ W_rel2 (4-dim) instead of h1 (16-dim).
// ---------------------------------------------------------------------------
__global__ __launch_bounds__(128) void conv_kernel(
    const float* __restrict__ x,      const int*   __restrict__ eidx,
    const float* __restrict__ eattr,
    const float* __restrict__ W_rel1, const float* __restrict__ b1,
    const float* __restrict__ W_root1,
    const float* __restrict__ W_rel2, const float* __restrict__ b2,
    const float* __restrict__ W_root2)
{
    __shared__ __align__(16) float xbuf[2][NPG * 8];
    __shared__ __align__(16) int   sbuf[2][EPG];
    __shared__ __align__(16) int   dbuf[2][EPG];
    __shared__ __align__(16) float ebuf[2][EPG];
    __shared__ float wsm[404];
    __shared__ float agg[NPG * 8];     // conv1 aggregation (8-dim)
    __shared__ float h1s[NPG * 16];
    __shared__ float ps[NPG * 4];      // h1 @ W_rel2
    __shared__ float rrs[NPG * 4];     // b2 + h1 @ W_root2
    __shared__ float agg2[NPG * 4];    // conv2 aggregation (4-dim)

    const int t = threadIdx.x;

    // stage weights once: Wrel1@0(128) b1@128(16) Wroot1@144(128)
    //                     Wrel2@272(64) b2@336(4) Wroot2@340(64)
    {
        if (t < 128) wsm[t]       = W_rel1[t];
        if (t < 16)  wsm[128 + t] = b1[t];
        if (t < 128) wsm[144 + t] = W_root1[t];
        if (t < 64)  wsm[272 + t] = W_rel2[t];
        if (t < 4)   wsm[336 + t] = b2[t];
        if (t < 64)  wsm[340 + t] = W_root2[t];
    }
    for (int i = t; i < NPG * 8; i += 128) agg[i] = 0.f;
    for (int i = t; i < NPG * 4; i += 128) agg2[i] = 0.f;

    const int g0 = blockIdx.x * GPC;

    // ---- prefetch graph 0 ----
    {
        const int g = g0;
        if (t < NPG * 2) cpa16(&xbuf[0][t * 4], x + (size_t)g * NPG * 8 + t * 4);
        if (t < EPG / 4) {
            cpa16(&sbuf[0][t * 4], eidx + (size_t)g * EPG + t * 4);
            cpa16(&dbuf[0][t * 4], eidx + (size_t)EDGES_TOTAL + (size_t)g * EPG + t * 4);
            cpa16(&ebuf[0][t * 4], eattr + (size_t)g * EPG + t * 4);
        }
        CP_COMMIT();
    }

    for (int it = 0; it < GPC; it++) {
        const int g = g0 + it;
        const int b = it & 1;
        const int base = g * NPG;

        CP_WAIT0();
        __syncthreads();

        // prefetch next graph into other buffer (overlaps with compute)
        if (it + 1 < GPC) {
            const int gn = g + 1, bn = b ^ 1;
            if (t < NPG * 2) cpa16(&xbuf[bn][t * 4], x + (size_t)gn * NPG * 8 + t * 4);
            if (t < EPG / 4) {
                cpa16(&sbuf[bn][t * 4], eidx + (size_t)gn * EPG + t * 4);
                cpa16(&dbuf[bn][t * 4], eidx + (size_t)EDGES_TOTAL + (size_t)gn * EPG + t * 4);
                cpa16(&ebuf[bn][t * 4], eattr + (size_t)gn * EPG + t * 4);
            }
            CP_COMMIT();
        }

        // ---- phase 1: conv1 aggregation (8-dim smem atomics) ----
        for (int i = t; i < EPG * 8; i += 128) {
            int e = i >> 3, f = i & 7;
            int s = sbuf[b][e] - base, d = dbuf[b][e] - base;
            atomicAdd(&agg[d * 8 + f], ebuf[b][e] * xbuf[b][s * 8 + f]);
        }
        __syncthreads();

        // ---- phase 2: h1 = relu(agg@Wrel1 + b1 + x@Wroot1); zero agg2 ----
        for (int i = t; i < NPG * 16; i += 128) {
            int v = i >> 4, o = i & 15;
            float a = wsm[128 + o];
            #pragma unroll
            for (int c = 0; c < 8; c++)
                a += agg[v * 8 + c] * wsm[c * 16 + o]
                   + xbuf[b][v * 8 + c] * wsm[144 + c * 16 + o];
            h1s[i] = fmaxf(a, 0.f);
        }
        for (int i = t; i < NPG * 4; i += 128) agg2[i] = 0.f;
        __syncthreads();

        // ---- phase 3: p = h1@Wrel2, rr = b2 + h1@Wroot2; zero agg ----
        for (int i = t; i < NPG * 4; i += 128) {
            int v = i >> 2, o = i & 3;
            float pa = 0.f, ra = wsm[336 + o];
            #pragma unroll
            for (int c = 0; c < 16; c++) {
                float h = h1s[v * 16 + c];
                pa += h * wsm[272 + c * 4 + o];
                ra += h * wsm[340 + c * 4 + o];
            }
            ps[i] = pa; rrs[i] = ra;
        }
        for (int i = t; i < NPG * 8; i += 128) agg[i] = 0.f;
        __syncthreads();

        // ---- phase 4: conv2 aggregation in 4-dim ----
        for (int i = t; i < EPG * 4; i += 128) {
            int e = i >> 2, f = i & 3;
            int s = sbuf[b][e] - base, d = dbuf[b][e] - base;
            atomicAdd(&agg2[d * 4 + f], ebuf[b][e] * ps[s * 4 + f]);
        }
        __syncthreads();

        // ---- phase 5: h2 = relu(agg2 + rr) -> g_concat (no sync needed;
        //      next iteration's loop-top sync orders everything) ----
        float* op = g_concat + (size_t)g * CPAD;
        for (int i = t; i < NPG * 4; i += 128)
            op[i] = fmaxf(agg2[i] + rrs[i], 0.f);
    }
}

// ---------------------------------------------------------------------------
// Kernel B: out = sigmoid(relu(concat @ Wo1 + bo1) @ Wo2 + bo2)
// fp32 GEMM with packed fma.rn.f32x2. Full Wo1 (226x128) + 64 rows in smem.
// 512 threads: warp w owns 4 rows, lane owns 4 columns (2 f32x2 pairs).
// ---------------------------------------------------------------------------
__global__ __launch_bounds__(512) void mlp_kernel(
    const float* __restrict__ Wo1, const float* __restrict__ bo1,
    const float* __restrict__ Wo2, const float* __restrict__ bo2,
    float* __restrict__ out)
{
    extern __shared__ float sm[];
    float* ws  = sm;                 // [226*128]
    float* ins = sm + CONCAT * 128;  // [64*228]

    const int t  = threadIdx.x;
    const int g0 = blockIdx.x * TB;

    {
        const float4* wsrc = (const float4*)Wo1;
        float4*       wdst = (float4*)ws;
        for (int i = t; i < CONCAT * 128 / 4; i += 512) wdst[i] = wsrc[i];
        const float4* csrc = (const float4*)(g_concat + (size_t)g0 * CPAD);
        float4*       cdst = (float4*)ins;
        for (int i = t; i < TB * CPAD / 4; i += 512) cdst[i] = csrc[i];
    }
    __syncthreads();

    const int lane = t & 31;
    const int wp   = t >> 5;
    const int j0   = lane * 4;      // 4 output columns (2 f32x2 pairs)
    const int r0   = wp * 4;        // 4 rows per warp (16 warps x 4 = 64)

    unsigned long long acc[4][2];
    #pragma unroll
    for (int r = 0; r < 4; r++) { acc[r][0] = pk(0.f, 0.f); acc[r][1] = pk(0.f, 0.f); }

    for (int kb = 0; kb < 224; kb += 4) {
        float4 v4[4];
        #pragma unroll
        for (int r = 0; r < 4; r++)
            v4[r] = *(const float4*)&ins[(r0 + r) * CPAD + kb];
        #pragma unroll
        for (int kk = 0; kk < 4; kk++) {
            const float4 w = *(const float4*)&ws[(kb + kk) * 128 + j0];
            const unsigned long long w01 = pk(w.x, w.y);
            const unsigned long long w23 = pk(w.z, w.w);
            #pragma unroll
            for (int r = 0; r < 4; r++) {
                const float v = ((const float*)&v4[r])[kk];
                const unsigned long long vv = pk(v, v);
                acc[r][0] = f2fma(vv, w01, acc[r][0]);
                acc[r][1] = f2fma(vv, w23, acc[r][1]);
            }
        }
    }
    // remainder k = 224, 225
    #pragma unroll
    for (int k = 224; k < CONCAT; k++) {
        const float4 w = *(const float4*)&ws[k * 128 + j0];
        const unsigned long long w01 = pk(w.x, w.y);
        const unsigned long long w23 = pk(w.z, w.w);
        #pragma unroll
        for (int r = 0; r < 4; r++) {
            const float v = ins[(r0 + r) * CPAD + k];
            const unsigned long long vv = pk(v, v);
            acc[r][0] = f2fma(vv, w01, acc[r][0]);
            acc[r][1] = f2fma(vv, w23, acc[r][1]);
        }
    }

    const float4 bv  = *(const float4*)&bo1[j0];
    const float4 wv  = *(const float4*)&Wo2[j0];
    const float bo2s = bo2[0];

    #pragma unroll
    for (int r = 0; r < 4; r++) {
        float a0, a1, a2, a3;
        upk(acc[r][0], a0, a1);
        upk(acc[r][1], a2, a3);
        float p = fmaxf(a0 + bv.x, 0.f) * wv.x
                + fmaxf(a1 + bv.y, 0.f) * wv.y
                + fmaxf(a2 + bv.z, 0.f) * wv.z
                + fmaxf(a3 + bv.w, 0.f) * wv.w;
        #pragma unroll
        for (int off = 16; off; off >>= 1)
            p += __shfl_down_sync(0xffffffffu, p, off);
        if (lane == 0)
            out[g0 + r0 + r] = 1.f / (1.f + expf(-(p + bo2s)));
    }
}

// ---------------------------------------------------------------------------
extern "C" void kernel_launch(void* const* d_in, const int* in_sizes, int n_in,
                              void* d_out, int out_size)
{
    const float* x       = (const float*)d_in[0];
    const int*   eidx    = (const int*)  d_in[1];
    const float* eattr   = (const float*)d_in[2];
    const float* gfeat   = (const float*)d_in[3];
    const float* W_rel1  = (const float*)d_in[4];
    const float* b1      = (const float*)d_in[5];
    const float* W_root1 = (const float*)d_in[6];
    const float* W_rel2  = (const float*)d_in[7];
    const float* b2      = (const float*)d_in[8];
    const float* W_root2 = (const float*)d_in[9];
    const float* Wg1     = (const float*)d_in[10];
    const float* bg1     = (const float*)d_in[11];
    const float* Wg2     = (const float*)d_in[12];
    const float* bg2     = (const float*)d_in[13];
    const float* Wg3     = (const float*)d_in[14];
    const float* bg3     = (const float*)d_in[15];
    const float* Wo1     = (const float*)d_in[16];
    const float* bo1     = (const float*)d_in[17];
    const float* Wo2     = (const float*)d_in[18];
    const float* bo2     = (const float*)d_in[19];
    // d_in[20] = isTrain (eval mode: dropout is identity)

    glob_kernel<<<BATCH / 256, 256>>>(gfeat, Wg1, bg1, Wg2, bg2, Wg3, bg3);
    conv_kernel<<<BATCH / GPC, 128>>>(x, eidx, eattr,
                                      W_rel1, b1, W_root1, W_rel2, b2, W_root2);

    const int smem_bytes = (CONCAT * 128 + TB * CPAD) * (int)sizeof(float);
    cudaFuncSetAttribute(mlp_kernel, cudaFuncAttributeMaxDynamicSharedMemorySize,
                         smem_bytes);
    mlp_kernel<<<BATCH / TB, 512, smem_bytes>>>(Wo1, bo1, Wo2, bo2,
                                                (float*)d_out);
}

// round 6
// speedup vs baseline: 1.3220x; 1.1127x over previous
#include <cuda_runtime.h>

#define BATCH  32768
#define NPG    54
#define EPG    144
#define GLOB   10
#define CONCAT 226
#define CPAD   228   // padded row stride (16B multiple) for g_concat
#define EDGES_TOTAL (BATCH*EPG)
#define TB     64    // rows per CTA in out-MLP GEMM
#define GPC    32    // graphs per conv CTA (32768 = 1024 * 32)

// Scratch for the [B, 228] padded concat activations (device global).
// Only columns [0,216) are written by conv; [216,226) computed inside mlp.
static __device__ __align__(16) float g_concat[(size_t)BATCH * CPAD];

typedef unsigned long long u64;

// ---------------- packed f32x2 helpers (sm_103a) ----------------
__device__ __forceinline__ u64 pk(float lo, float hi) {
    u64 r; asm("mov.b64 %0, {%1,%2};" : "=l"(r) : "f"(lo), "f"(hi)); return r;
}
__device__ __forceinline__ u64 f2fma(u64 a, u64 b, u64 c) {
    u64 d; asm("fma.rn.f32x2 %0, %1, %2, %3;" : "=l"(d) : "l"(a), "l"(b), "l"(c));
    return d;
}
__device__ __forceinline__ void upk(u64 v, float& lo, float& hi) {
    asm("mov.b64 {%0,%1}, %2;" : "=f"(lo), "=f"(hi) : "l"(v));
}

// ---------------- cp.async helpers ----------------
__device__ __forceinline__ void cpa16(void* s, const void* g) {
    unsigned ss = (unsigned)__cvta_generic_to_shared(s);
    asm volatile("cp.async.ca.shared.global [%0], [%1], 16;\n" :: "r"(ss), "l"(g));
}
#define CP_COMMIT() asm volatile("cp.async.commit_group;\n" ::: "memory")
#define CP_WAIT0()  asm volatile("cp.async.wait_group 0;\n" ::: "memory")

// ---------------------------------------------------------------------------
// Kernel A: persistent fused GraphConv1 -> relu -> GraphConv2 -> relu.
// 1024 CTAs x 128 threads, GPC graphs each, cp.async double-buffered inputs.
// Per graph: build CSR once (288 smem atomics), then BOTH aggregations are
// atomic-free gathers. Conv2 aggregates p = h1 @ W_rel2 (4-dim, linearity).
// ---------------------------------------------------------------------------
__global__ __launch_bounds__(128) void conv_kernel(
    const float* __restrict__ x,      const int*   __restrict__ eidx,
    const float* __restrict__ eattr,
    const float* __restrict__ W_rel1, const float* __restrict__ b1,
    const float* __restrict__ W_root1,
    const float* __restrict__ W_rel2, const float* __restrict__ b2,
    const float* __restrict__ W_root2)
{
    __shared__ __align__(16) float xbuf[2][NPG * 8];
    __shared__ __align__(16) int   sbuf[2][EPG];
    __shared__ __align__(16) int   dbuf[2][EPG];
    __shared__ __align__(16) float ebuf[2][EPG];
    __shared__ __align__(16) float wsm[404];
    __shared__ int   cnt[NPG];          // degree counts (zeroed for next graph)
    __shared__ int   off[NPG];          // exclusive CSR offsets (off[54]=144)
    __shared__ int   pos[NPG];          // scatter cursors
    __shared__ int   psrc[EPG];         // CSR: local src per slot
    __shared__ float pwt[EPG];          // CSR: edge weight per slot
    __shared__ __align__(16) float agg[NPG * 8];
    __shared__ __align__(16) float h1s[NPG * 16];
    __shared__ __align__(16) float ps[NPG * 4];
    __shared__ __align__(16) float rrs[NPG * 4];

    const int t = threadIdx.x;

    // stage weights once: Wrel1@0(128) b1@128(16) Wroot1@144(128)
    //                     Wrel2@272(64) b2@336(4) Wroot2@340(64)
    if (t < 128) wsm[t]       = W_rel1[t];
    if (t < 16)  wsm[128 + t] = b1[t];
    if (t < 128) wsm[144 + t] = W_root1[t];
    if (t < 64)  wsm[272 + t] = W_rel2[t];
    if (t < 4)   wsm[336 + t] = b2[t];
    if (t < 64)  wsm[340 + t] = W_root2[t];
    if (t < NPG) cnt[t] = 0;

    const int g0 = blockIdx.x * GPC;

    // ---- prefetch graph 0 ----
    if (t < NPG * 2) cpa16(&xbuf[0][t * 4], x + (size_t)g0 * NPG * 8 + t * 4);
    if (t < EPG / 4) {
        cpa16(&sbuf[0][t * 4], eidx + (size_t)g0 * EPG + t * 4);
        cpa16(&dbuf[0][t * 4], eidx + (size_t)EDGES_TOTAL + (size_t)g0 * EPG + t * 4);
        cpa16(&ebuf[0][t * 4], eattr + (size_t)g0 * EPG + t * 4);
    }
    CP_COMMIT();

    for (int it = 0; it < GPC; it++) {
        const int g = g0 + it;
        const int b = it & 1;
        const int base = g * NPG;

        CP_WAIT0();
        __syncthreads();                               // B-top

        // prefetch next graph into other buffer (overlaps with compute)
        if (it + 1 < GPC) {
            const int gn = g + 1, bn = b ^ 1;
            if (t < NPG * 2) cpa16(&xbuf[bn][t * 4], x + (size_t)gn * NPG * 8 + t * 4);
            if (t < EPG / 4) {
                cpa16(&sbuf[bn][t * 4], eidx + (size_t)gn * EPG + t * 4);
                cpa16(&dbuf[bn][t * 4], eidx + (size_t)EDGES_TOTAL + (size_t)gn * EPG + t * 4);
                cpa16(&ebuf[bn][t * 4], eattr + (size_t)gn * EPG + t * 4);
            }
            CP_COMMIT();
        }

        // ---- CSR 1: count in-degrees ----
        for (int e = t; e < EPG; e += 128)
            atomicAdd(&cnt[dbuf[b][e] - base], 1);
        __syncthreads();                               // B2

        // ---- CSR 2: exclusive scan by warp 0 (54 elems, 2 segments) ----
        if (t < 32) {
            const unsigned m = 0xffffffffu;
            int c0 = cnt[t];
            int c1 = (t < NPG - 32) ? cnt[t + 32] : 0;
            int s0 = c0, s1 = c1;
            #pragma unroll
            for (int d2 = 1; d2 < 32; d2 <<= 1) {
                int n0 = __shfl_up_sync(m, s0, d2);
                int n1 = __shfl_up_sync(m, s1, d2);
                if (t >= d2) { s0 += n0; s1 += n1; }
            }
            int tot0 = __shfl_sync(m, s0, 31);
            s1 += tot0;
            int e0 = s0 - c0;
            off[t] = e0; pos[t] = e0;
            if (t < NPG - 32) {
                int e1 = s1 - c1;
                off[t + 32] = e1; pos[t + 32] = e1;
            }
        }
        __syncthreads();                               // B3

        // ---- CSR 3: scatter (src, weight) into slots ----
        for (int e = t; e < EPG; e += 128) {
            int d = dbuf[b][e] - base;
            int slot = atomicAdd(&pos[d], 1);
            psrc[slot] = sbuf[b][e] - base;
            pwt[slot]  = ebuf[b][e];
        }
        __syncthreads();                               // B4

        // ---- gather 1: agg[v][0..7] = sum_{edges->v} w * x[src]  (f32x2) ----
        for (int item = t; item < NPG * 4; item += 128) {
            int v = item >> 2, fp = item & 3;
            int j0 = off[v];
            int j1 = (v < NPG - 1) ? off[v + 1] : EPG;
            u64 acc = pk(0.f, 0.f);
            for (int j = j0; j < j1; j++) {
                int s = psrc[j];
                float w = pwt[j];
                u64 xv = *(const u64*)&xbuf[b][s * 8 + fp * 2];
                acc = f2fma(pk(w, w), xv, acc);
            }
            *(u64*)&agg[v * 8 + fp * 2] = acc;
        }
        __syncthreads();                               // B5

        // ---- h1 = relu(agg@Wrel1 + b1 + x@Wroot1) : f32x2, zero cnt ----
        for (int item = t; item < NPG * 8; item += 128) {
            int v = item >> 3, op2 = item & 7;        // output pair (2 of 16)
            u64 acc = *(const u64*)&wsm[128 + op2 * 2];
            #pragma unroll
            for (int c = 0; c < 8; c++) {
                float av = agg[v * 8 + c];
                float xv = xbuf[b][v * 8 + c];
                acc = f2fma(pk(av, av), *(const u64*)&wsm[c * 16 + op2 * 2], acc);
                acc = f2fma(pk(xv, xv), *(const u64*)&wsm[144 + c * 16 + op2 * 2], acc);
            }
            float lo, hi; upk(acc, lo, hi);
            h1s[v * 16 + op2 * 2]     = fmaxf(lo, 0.f);
            h1s[v * 16 + op2 * 2 + 1] = fmaxf(hi, 0.f);
        }
        if (t < NPG) cnt[t] = 0;                      // ready for next graph
        __syncthreads();                               // B6

        // ---- p = h1@Wrel2, rr = b2 + h1@Wroot2 : f32x2 ----
        for (int item = t; item < NPG * 2; item += 128) {
            int v = item >> 1, op2 = item & 1;        // pair of 4 outputs
            u64 pa = pk(0.f, 0.f);
            u64 ra = *(const u64*)&wsm[336 + op2 * 2];
            #pragma unroll
            for (int c = 0; c < 16; c++) {
                float h = h1s[v * 16 + c];
                u64 hh = pk(h, h);
                pa = f2fma(hh, *(const u64*)&wsm[272 + c * 4 + op2 * 2], pa);
                ra = f2fma(hh, *(const u64*)&wsm[340 + c * 4 + op2 * 2], ra);
            }
            *(u64*)&ps[v * 4 + op2 * 2]  = pa;
            *(u64*)&rrs[v * 4 + op2 * 2] = ra;
        }
        __syncthreads();                               // B7

        // ---- gather 2 + epilogue: h2 = relu(sum w*p[src] + rr) -> gmem ----
        float* opr = g_concat + (size_t)g * CPAD;
        for (int item = t; item < NPG * 2; item += 128) {
            int v = item >> 1, fp = item & 1;
            int j0 = off[v];
            int j1 = (v < NPG - 1) ? off[v + 1] : EPG;
            u64 acc = *(const u64*)&rrs[v * 4 + fp * 2];
            for (int j = j0; j < j1; j++) {
                int s = psrc[j];
                float w = pwt[j];
                acc = f2fma(pk(w, w), *(const u64*)&ps[s * 4 + fp * 2], acc);
            }
            float lo, hi; upk(acc, lo, hi);
            float2 o2 = make_float2(fmaxf(lo, 0.f), fmaxf(hi, 0.f));
            *(float2*)&opr[v * 4 + fp * 2] = o2;
        }
        // no barrier here: loop-top barrier orders everything
    }
}

// ---------------------------------------------------------------------------
// Kernel B: per-row global MLP (10->8->8->10) fused with
// out = sigmoid(relu(concat @ Wo1 + bo1) @ Wo2 + bo2).
// fp32 GEMM with packed fma.rn.f32x2. Full Wo1 (226x128) + 64 rows in smem.
// 512 threads: warp w owns 4 rows, lane owns 4 columns (2 f32x2 pairs).
// ---------------------------------------------------------------------------
__global__ __launch_bounds__(512) void mlp_kernel(
    const float* __restrict__ Wo1, const float* __restrict__ bo1,
    const float* __restrict__ Wo2, const float* __restrict__ bo2,
    const float* __restrict__ gfeat,
    const float* __restrict__ Wg1, const float* __restrict__ bg1,
    const float* __restrict__ Wg2, const float* __restrict__ bg2,
    const float* __restrict__ Wg3, const float* __restrict__ bg3,
    float* __restrict__ out)
{
    extern __shared__ float sm[];
    float* ws  = sm;                         // [226*128]
    float* ins = ws + CONCAT * 128;          // [64*228]
    float* gws = ins + TB * CPAD;            // [250] global-MLP weights
    float* gfs = gws + 256;                  // [64*10] global feats

    const int t  = threadIdx.x;
    const int g0 = blockIdx.x * TB;

    {
        const float4* wsrc = (const float4*)Wo1;
        float4*       wdst = (float4*)ws;
        for (int i = t; i < CONCAT * 128 / 4; i += 512) wdst[i] = wsrc[i];
        const float4* csrc = (const float4*)(g_concat + (size_t)g0 * CPAD);
        float4*       cdst = (float4*)ins;
        for (int i = t; i < TB * CPAD / 4; i += 512) cdst[i] = csrc[i];
        // global-MLP weights: Wg1 80@0, bg1 8@80, Wg2 64@88, bg2 8@152,
        //                     Wg3 80@160, bg3 10@240
        if (t < 80)  gws[t]       = Wg1[t];
        if (t < 8)   gws[80 + t]  = bg1[t];
        if (t < 64)  gws[88 + t]  = Wg2[t];
        if (t < 8)   gws[152 + t] = bg2[t];
        if (t < 80)  gws[160 + t] = Wg3[t];
        if (t < 10)  gws[240 + t] = bg3[t];
        // 64 rows x 10 global feats (640 floats, base g0*40B = 16B multiple)
        const float4* gsrc = (const float4*)(gfeat + (size_t)g0 * GLOB);
        float4*       gdst = (float4*)gfs;
        for (int i = t; i < TB * GLOB / 4; i += 512) gdst[i] = gsrc[i];
    }
    __syncthreads();

    // ---- per-row global MLP into ins[r*CPAD + 216..225] ----
    if (t < TB) {
        const float* gi = gfs + t * GLOB;
        float a1[8];
        #pragma unroll
        for (int o = 0; o < 8; o++) {
            float a = gws[80 + o];
            #pragma unroll
            for (int i = 0; i < GLOB; i++) a += gi[i] * gws[i * 8 + o];
            a1[o] = fmaxf(a, 0.f);
        }
        float a2[8];
        #pragma unroll
        for (int o = 0; o < 8; o++) {
            float a = gws[152 + o];
            #pragma unroll
            for (int i = 0; i < 8; i++) a += a1[i] * gws[88 + i * 8 + o];
            a2[o] = fmaxf(a, 0.f);
        }
        float* dst = ins + t * CPAD + NPG * 4;
        #pragma unroll
        for (int o = 0; o < GLOB; o++) {
            float a = gws[240 + o];
            #pragma unroll
            for (int i = 0; i < 8; i++) a += a2[i] * gws[160 + i * 10 + o];
            dst[o] = fmaxf(a, 0.f);
        }
    }
    __syncthreads();

    const int lane = t & 31;
    const int wp   = t >> 5;
    const int j0   = lane * 4;      // 4 output columns (2 f32x2 pairs)
    const int r0   = wp * 4;        // 4 rows per warp (16 warps x 4 = 64)

    u64 acc[4][2];
    #pragma unroll
    for (int r = 0; r < 4; r++) { acc[r][0] = pk(0.f, 0.f); acc[r][1] = pk(0.f, 0.f); }

    for (int kb = 0; kb < 224; kb += 4) {
        float4 v4[4];
        #pragma unroll
        for (int r = 0; r < 4; r++)
            v4[r] = *(const float4*)&ins[(r0 + r) * CPAD + kb];
        #pragma unroll
        for (int kk = 0; kk < 4; kk++) {
            const float4 w = *(const float4*)&ws[(kb + kk) * 128 + j0];
            const u64 w01 = pk(w.x, w.y);
            const u64 w23 = pk(w.z, w.w);
            #pragma unroll
            for (int r = 0; r < 4; r++) {
                const float v = ((const float*)&v4[r])[kk];
                const u64 vv = pk(v, v);
                acc[r][0] = f2fma(vv, w01, acc[r][0]);
                acc[r][1] = f2fma(vv, w23, acc[r][1]);
            }
        }
    }
    #pragma unroll
    for (int k = 224; k < CONCAT; k++) {
        const float4 w = *(const float4*)&ws[k * 128 + j0];
        const u64 w01 = pk(w.x, w.y);
        const u64 w23 = pk(w.z, w.w);
        #pragma unroll
        for (int r = 0; r < 4; r++) {
            const float v = ins[(r0 + r) * CPAD + k];
            const u64 vv = pk(v, v);
            acc[r][0] = f2fma(vv, w01, acc[r][0]);
            acc[r][1] = f2fma(vv, w23, acc[r][1]);
        }
    }

    const float4 bv  = *(const float4*)&bo1[j0];
    const float4 wv  = *(const float4*)&Wo2[j0];
    const float bo2s = bo2[0];

    #pragma unroll
    for (int r = 0; r < 4; r++) {
        float a0, a1, a2, a3;
        upk(acc[r][0], a0, a1);
        upk(acc[r][1], a2, a3);
        float p = fmaxf(a0 + bv.x, 0.f) * wv.x
                + fmaxf(a1 + bv.y, 0.f) * wv.y
                + fmaxf(a2 + bv.z, 0.f) * wv.z
                + fmaxf(a3 + bv.w, 0.f) * wv.w;
        #pragma unroll
        for (int off = 16; off; off >>= 1)
            p += __shfl_down_sync(0xffffffffu, p, off);
        if (lane == 0)
            out[g0 + r0 + r] = 1.f / (1.f + expf(-(p + bo2s)));
    }
}

// ---------------------------------------------------------------------------
extern "C" void kernel_launch(void* const* d_in, const int* in_sizes, int n_in,
                              void* d_out, int out_size)
{
    const float* x       = (const float*)d_in[0];
    const int*   eidx    = (const int*)  d_in[1];
    const float* eattr   = (const float*)d_in[2];
    const float* gfeat   = (const float*)d_in[3];
    const float* W_rel1  = (const float*)d_in[4];
    const float* b1      = (const float*)d_in[5];
    const float* W_root1 = (const float*)d_in[6];
    const float* W_rel2  = (const float*)d_in[7];
    const float* b2      = (const float*)d_in[8];
    const float* W_root2 = (const float*)d_in[9];
    const float* Wg1     = (const float*)d_in[10];
    const float* bg1     = (const float*)d_in[11];
    const float* Wg2     = (const float*)d_in[12];
    const float* bg2     = (const float*)d_in[13];
    const float* Wg3     = (const float*)d_in[14];
    const float* bg3     = (const float*)d_in[15];
    const float* Wo1     = (const float*)d_in[16];
    const float* bo1     = (const float*)d_in[17];
    const float* Wo2     = (const float*)d_in[18];
    const float* bo2     = (const float*)d_in[19];
    // d_in[20] = isTrain (eval mode: dropout is identity)

    conv_kernel<<<BATCH / GPC, 128>>>(x, eidx, eattr,
                                      W_rel1, b1, W_root1, W_rel2, b2, W_root2);

    const int smem_bytes = (CONCAT * 128 + TB * CPAD + 256 + TB * GLOB)
                           * (int)sizeof(float);
    cudaFuncSetAttribute(mlp_kernel, cudaFuncAttributeMaxDynamicSharedMemorySize,
                         smem_bytes);
    mlp_kernel<<<BATCH / TB, 512, smem_bytes>>>(Wo1, bo1, Wo2, bo2,
                                                gfeat, Wg1, bg1, Wg2, bg2,
                                                Wg3, bg3, (float*)d_out);
}